// round 1
// baseline (speedup 1.0000x reference)
#include <cuda_runtime.h>
#include <math.h>

#define MAXN 50048
#define KIN 128          // 120 + 8 input features
#define HID 64           // H1 * D1
#define NH 8             // heads layer 1
#define C2 40            // out channels
#define NEG 0.2f

// ---------------- scratch (static device globals; no allocs allowed) ----------------
__device__ float g_h1[MAXN * HID];     // layer-1 transformed features
__device__ float g_alS1[MAXN * NH];    // per-head src logits
__device__ float g_alD1[MAXN * NH];    // per-head dst logits
__device__ float g_acc1[MAXN * HID];   // layer-1 aggregation accumulator -> becomes h (after ELU)
__device__ float g_s1[MAXN * NH];      // layer-1 softmax denominators
__device__ float g_h2[MAXN * C2];      // layer-2 transformed features
__device__ float g_alS2[MAXN];
__device__ float g_alD2[MAXN];
__device__ float g_acc2[MAXN * C2];
__device__ float g_s2[MAXN];

// ---------------- zero accumulators ----------------
__global__ void zero_k(int n) {
    int tot = n * (HID + C2 + NH + 1);
    int stride = gridDim.x * blockDim.x;
    for (int i = blockIdx.x * blockDim.x + threadIdx.x; i < tot; i += stride) {
        int j = i;
        if (j < n * HID) { g_acc1[j] = 0.f; continue; }
        j -= n * HID;
        if (j < n * C2) { g_acc2[j] = 0.f; continue; }
        j -= n * C2;
        if (j < n * NH) { g_s1[j] = 0.f; continue; }
        j -= n * NH;
        g_s2[j] = 0.f;
    }
}

// ---------------- layer 1 GEMM: [N,128] @ [128,64] + attention logits ----------------
// block: 256 threads, 16 rows per block. thread t: col = t&63, row-group = t>>6 (4 rows each)
__global__ void gemm1_k(const float* __restrict__ x, const float* __restrict__ topo,
                        const float* __restrict__ W1,
                        const float* __restrict__ a_src, const float* __restrict__ a_dst,
                        int n) {
    __shared__ float sW[KIN * HID];   // 32 KB
    __shared__ float sX[16 * KIN];    // 8 KB
    __shared__ float sH[16 * HID];    // 4 KB
    int t = threadIdx.x;
    for (int i = t; i < KIN * HID; i += 256) sW[i] = W1[i];
    int row0 = blockIdx.x * 16;
    for (int i = t; i < 16 * KIN; i += 256) {
        int r = i >> 7, c = i & 127;
        int gr = row0 + r;
        float v = 0.f;
        if (gr < n) v = (c < 120) ? x[gr * 120 + c] : topo[gr * 8 + (c - 120)];
        sX[i] = v;
    }
    __syncthreads();
    int col = t & 63;
    int rg = t >> 6;  // 0..3
    float acc[4] = {0.f, 0.f, 0.f, 0.f};
#pragma unroll 4
    for (int k = 0; k < KIN; k++) {
        float w = sW[k * HID + col];
#pragma unroll
        for (int r = 0; r < 4; r++) acc[r] += sX[(rg * 4 + r) * KIN + k] * w;
    }
#pragma unroll
    for (int r = 0; r < 4; r++) {
        int lr = rg * 4 + r;
        int gr = row0 + lr;
        sH[lr * HID + col] = acc[r];
        if (gr < n) g_h1[gr * HID + col] = acc[r];
    }
    __syncthreads();
    // attention logits: 128 threads -> (row, head)
    if (t < 128) {
        int r = t >> 3, hd = t & 7;
        int gr = row0 + r;
        if (gr < n) {
            float ss = 0.f, sd = 0.f;
#pragma unroll
            for (int d = 0; d < 8; d++) {
                float hv = sH[r * HID + hd * 8 + d];
                ss += hv * a_src[hd * 8 + d];
                sd += hv * a_dst[hd * 8 + d];
            }
            g_alS1[gr * NH + hd] = ss;
            g_alD1[gr * NH + hd] = sd;
        }
    }
}

// ---------------- layer 1 edge aggregation (warp per edge) ----------------
__global__ void edge1_k(const int* __restrict__ ei, int E, int Etot) {
    int w = (blockIdx.x * blockDim.x + threadIdx.x) >> 5;
    if (w >= Etot) return;
    int l = threadIdx.x & 31;
    int src, dst;
    if (w < E) { src = ei[w]; dst = ei[E + w]; }
    else       { src = dst = w - E; }
    int h0 = l >> 3;      // heads 0..3 for features l
    int h1i = h0 + 4;     // heads 4..7 for features l+32
    float e0 = g_alS1[src * NH + h0] + g_alD1[dst * NH + h0];
    e0 = e0 > 0.f ? e0 : NEG * e0;
    float p0 = __expf(e0);
    float e1 = g_alS1[src * NH + h1i] + g_alD1[dst * NH + h1i];
    e1 = e1 > 0.f ? e1 : NEG * e1;
    float p1 = __expf(e1);
    atomicAdd(&g_acc1[dst * HID + l],      p0 * g_h1[src * HID + l]);
    atomicAdd(&g_acc1[dst * HID + 32 + l], p1 * g_h1[src * HID + 32 + l]);
    if ((l & 7) == 0) {
        atomicAdd(&g_s1[dst * NH + h0],  p0);
        atomicAdd(&g_s1[dst * NH + h1i], p1);
    }
}

// ---------------- layer 1 finish: normalize + bias + ELU (in place) ----------------
__global__ void finish1_k(const float* __restrict__ b1, int n) {
    int i = blockIdx.x * blockDim.x + threadIdx.x;
    if (i >= n * HID) return;
    int node = i >> 6, f = i & 63;
    float v = g_acc1[i] / g_s1[node * NH + (f >> 3)] + b1[f];
    g_acc1[i] = v > 0.f ? v : expm1f(v);
}

// ---------------- layer 2 GEMM: [N,64] @ [64,40] + scalar attention logits ----------------
// block: 320 threads = 40 cols x 8 rows
__global__ void gemm2_k(const float* __restrict__ W2,
                        const float* __restrict__ a_src2, const float* __restrict__ a_dst2,
                        int n) {
    __shared__ float sW[HID * C2];   // 10 KB
    __shared__ float sX[8 * HID];    // 2 KB
    __shared__ float sRed[320];
    int t = threadIdx.x;
    for (int i = t; i < HID * C2; i += 320) sW[i] = W2[i];
    int row0 = blockIdx.x * 8;
    for (int i = t; i < 8 * HID; i += 320) {
        int r = i >> 6, c = i & 63;
        int gr = row0 + r;
        sX[i] = (gr < n) ? g_acc1[gr * HID + c] : 0.f;
    }
    __syncthreads();
    int c = t % C2, r = t / C2;
    float acc = 0.f;
#pragma unroll 8
    for (int k = 0; k < HID; k++) acc += sX[r * HID + k] * sW[k * C2 + c];
    int gr = row0 + r;
    if (gr < n) g_h2[gr * C2 + c] = acc;
    sRed[t] = acc * a_src2[c];
    __syncthreads();
    if (c == 0 && gr < n) {
        float s = 0.f;
        for (int j = 0; j < C2; j++) s += sRed[r * C2 + j];
        g_alS2[gr] = s;
    }
    __syncthreads();
    sRed[t] = acc * a_dst2[c];
    __syncthreads();
    if (c == 0 && gr < n) {
        float s = 0.f;
        for (int j = 0; j < C2; j++) s += sRed[r * C2 + j];
        g_alD2[gr] = s;
    }
}

// ---------------- layer 2 edge aggregation (warp per edge) ----------------
__global__ void edge2_k(const int* __restrict__ ei, int E, int Etot) {
    int w = (blockIdx.x * blockDim.x + threadIdx.x) >> 5;
    if (w >= Etot) return;
    int l = threadIdx.x & 31;
    int src, dst;
    if (w < E) { src = ei[w]; dst = ei[E + w]; }
    else       { src = dst = w - E; }
    float e = g_alS2[src] + g_alD2[dst];
    e = e > 0.f ? e : NEG * e;
    float p = __expf(e);
    atomicAdd(&g_acc2[dst * C2 + l], p * g_h2[src * C2 + l]);
    if (l < 8) atomicAdd(&g_acc2[dst * C2 + 32 + l], p * g_h2[src * C2 + 32 + l]);
    if (l == 0) atomicAdd(&g_s2[dst], p);
}

// ---------------- layer 2 finish: normalize + bias + log_softmax ----------------
__global__ void finish2_k(const float* __restrict__ b2, float* __restrict__ out, int n) {
    int w = (blockIdx.x * blockDim.x + threadIdx.x) >> 5;
    if (w >= n) return;
    int l = threadIdx.x & 31;
    float inv = 1.f / g_s2[w];
    float v0 = g_acc2[w * C2 + l] * inv + b2[l];
    float v1 = (l < 8) ? (g_acc2[w * C2 + 32 + l] * inv + b2[32 + l]) : -3.0e38f;
    float m = fmaxf(v0, v1);
#pragma unroll
    for (int o = 16; o; o >>= 1) m = fmaxf(m, __shfl_xor_sync(0xFFFFFFFFu, m, o));
    float s = __expf(v0 - m) + ((l < 8) ? __expf(v1 - m) : 0.f);
#pragma unroll
    for (int o = 16; o; o >>= 1) s += __shfl_xor_sync(0xFFFFFFFFu, s, o);
    float lse = logf(s) + m;
    out[w * C2 + l] = v0 - lse;
    if (l < 8) out[w * C2 + 32 + l] = v1 - lse;
}

// ---------------- launcher ----------------
extern "C" void kernel_launch(void* const* d_in, const int* in_sizes, int n_in,
                              void* d_out, int out_size) {
    const float* x     = (const float*)d_in[0];
    const float* topo  = (const float*)d_in[1];
    const int*   ei    = (const int*)d_in[2];
    const float* W1    = (const float*)d_in[3];
    const float* a_s1  = (const float*)d_in[4];
    const float* a_d1  = (const float*)d_in[5];
    const float* b1    = (const float*)d_in[6];
    const float* W2    = (const float*)d_in[7];
    const float* a_s2  = (const float*)d_in[8];
    const float* a_d2  = (const float*)d_in[9];
    const float* b2    = (const float*)d_in[10];
    float* out = (float*)d_out;

    int n = in_sizes[0] / 120;
    int E = in_sizes[2] / 2;
    int Etot = E + n;

    int zt = n * (HID + C2 + NH + 1);
    zero_k<<<(zt + 255) / 256, 256>>>(n);

    gemm1_k<<<(n + 15) / 16, 256>>>(x, topo, W1, a_s1, a_d1, n);

    edge1_k<<<(Etot * 32 + 255) / 256, 256>>>(ei, E, Etot);

    finish1_k<<<(n * HID + 255) / 256, 256>>>(b1, n);

    gemm2_k<<<(n + 7) / 8, 320>>>(W2, a_s2, a_d2, n);

    edge2_k<<<(Etot * 32 + 255) / 256, 256>>>(ei, E, Etot);

    finish2_k<<<(n * 32 + 255) / 256, 256>>>(b2, out, n);
}

// round 2
// speedup vs baseline: 2.8654x; 2.8654x over previous
#include <cuda_runtime.h>
#include <math.h>

#define MAXN 50048
#define MAXE 800000
#define KIN 128
#define HID 64
#define NH 8
#define C2 40
#define NEG 0.2f

// ---------------- scratch ----------------
__device__ float g_h1[MAXN * HID];
__device__ float g_alS1[MAXN * NH];
__device__ float g_alD1[MAXN * NH];
__device__ float g_hact[MAXN * HID];   // activated layer-1 output
__device__ float g_h2[MAXN * C2];
__device__ float g_alS2[MAXN];
__device__ float g_alD2[MAXN];
// CSR
__device__ int g_cnt[MAXN];
__device__ int g_incl[MAXN];
__device__ int g_rowstart[MAXN];
__device__ int g_wcur[MAXN];
__device__ int g_eidx[MAXE];
__device__ int g_bsum[64];
__device__ int g_bscan[64];

// ---------------- CSR build ----------------
__global__ void zero_cnt_k(int n) {
    int i = blockIdx.x * blockDim.x + threadIdx.x;
    if (i < n) g_cnt[i] = 0;
}

__global__ void count_k(const int* __restrict__ ei, int E) {
    int i = blockIdx.x * blockDim.x + threadIdx.x;
    if (i < E) atomicAdd(&g_cnt[ei[E + i]], 1);
}

__global__ void scanA_k(int n) {
    __shared__ int s[1024];
    int i = blockIdx.x * 1024 + threadIdx.x;
    s[threadIdx.x] = (i < n) ? g_cnt[i] : 0;
    __syncthreads();
#pragma unroll
    for (int o = 1; o < 1024; o <<= 1) {
        int t = 0;
        if (threadIdx.x >= o) t = s[threadIdx.x - o];
        __syncthreads();
        if (threadIdx.x >= o) s[threadIdx.x] += t;
        __syncthreads();
    }
    if (i < n) g_incl[i] = s[threadIdx.x];
    if (threadIdx.x == 1023) g_bsum[blockIdx.x] = s[1023];
}

__global__ void scanB_k(int nb) {
    if (threadIdx.x == 0) {
        int run = 0;
        for (int b = 0; b < nb; b++) { g_bscan[b] = run; run += g_bsum[b]; }
    }
}

__global__ void scanC_k(int n) {
    int i = blockIdx.x * blockDim.x + threadIdx.x;
    if (i < n) {
        int start = g_incl[i] - g_cnt[i] + g_bscan[i >> 10];
        g_rowstart[i] = start;
        g_wcur[i] = start;
    }
}

__global__ void scatter_k(const int* __restrict__ ei, int E) {
    int i = blockIdx.x * blockDim.x + threadIdx.x;
    if (i < E) {
        int dst = ei[E + i];
        int pos = atomicAdd(&g_wcur[dst], 1);
        g_eidx[pos] = ei[i];
    }
}

// ---------------- layer 1 GEMM: [N,128]@[128,64] + per-head logits ----------------
// 256 threads, 64 rows/block, each thread 4 rows x 4 cols. Dynamic smem 68KB.
__global__ __launch_bounds__(256) void gemm1_k(
        const float* __restrict__ x, const float* __restrict__ topo,
        const float* __restrict__ W1,
        const float* __restrict__ a_src, const float* __restrict__ a_dst, int n) {
    extern __shared__ float smem[];
    float* sW  = smem;           // 128*64
    float* sX  = smem + 8192;    // 64*128
    float* sLS = smem + 16384;   // 64*8
    float* sLD = smem + 16896;   // 64*8
    int t = threadIdx.x;
    int row0 = blockIdx.x * 64;
    for (int i = t; i < KIN * HID; i += 256) sW[i] = W1[i];
    for (int i = t; i < 64 * KIN; i += 256) {
        int r = i >> 7, c = i & 127;
        int gr = row0 + r;
        float v = 0.f;
        if (gr < n) v = (c < 120) ? x[gr * 120 + c] : topo[gr * 8 + (c - 120)];
        sX[i] = v;
    }
    for (int i = t; i < 512; i += 256) { sLS[i] = 0.f; sLD[i] = 0.f; }
    __syncthreads();

    int rg = t >> 4;      // 0..15 -> rows rg*4..+3
    int cg = t & 15;      // cols cg*4..+3
    float acc[4][4];
#pragma unroll
    for (int r = 0; r < 4; r++)
#pragma unroll
        for (int c = 0; c < 4; c++) acc[r][c] = 0.f;

    const float4* sW4 = reinterpret_cast<const float4*>(sW);
#pragma unroll 4
    for (int k = 0; k < KIN; k++) {
        float4 wv = sW4[k * 16 + cg];
        float xv0 = sX[(rg * 4 + 0) * KIN + k];
        float xv1 = sX[(rg * 4 + 1) * KIN + k];
        float xv2 = sX[(rg * 4 + 2) * KIN + k];
        float xv3 = sX[(rg * 4 + 3) * KIN + k];
#define STEP(r, xv) \
        acc[r][0] += xv * wv.x; acc[r][1] += xv * wv.y; \
        acc[r][2] += xv * wv.z; acc[r][3] += xv * wv.w;
        STEP(0, xv0) STEP(1, xv1) STEP(2, xv2) STEP(3, xv3)
#undef STEP
    }

    // write h1, accumulate logit partials
    int hd = cg >> 1;
    int off = (cg & 1) * 4;
    float4* g_h1_4 = reinterpret_cast<float4*>(g_h1);
#pragma unroll
    for (int r = 0; r < 4; r++) {
        int lr = rg * 4 + r;
        int gr = row0 + lr;
        if (gr < n) {
            float4 o;
            o.x = acc[r][0]; o.y = acc[r][1]; o.z = acc[r][2]; o.w = acc[r][3];
            g_h1_4[gr * 16 + cg] = o;
        }
        float ps = 0.f, pd = 0.f;
#pragma unroll
        for (int j = 0; j < 4; j++) {
            ps += acc[r][j] * a_src[hd * 8 + off + j];
            pd += acc[r][j] * a_dst[hd * 8 + off + j];
        }
        atomicAdd(&sLS[lr * 8 + hd], ps);
        atomicAdd(&sLD[lr * 8 + hd], pd);
    }
    __syncthreads();
    for (int i = t; i < 512; i += 256) {
        int lr = i >> 3, h = i & 7;
        int gr = row0 + lr;
        if (gr < n) {
            g_alS1[gr * 8 + h] = sLS[i];
            g_alD1[gr * 8 + h] = sLD[i];
        }
    }
}

// ---------------- layer 1 aggregation: warp per dst node, fused normalize+bias+ELU ----------------
__global__ __launch_bounds__(256) void agg1_k(const float* __restrict__ b1, int n) {
    int w = (blockIdx.x * blockDim.x + threadIdx.x) >> 5;
    if (w >= n) return;
    int l = threadIdx.x & 31;
    int h0 = l >> 3;
    float alD = (l < 8) ? g_alD1[w * 8 + l] : 0.f;
    int beg = g_rowstart[w], cnt = g_cnt[w];
    float acc0 = 0.f, acc1 = 0.f, sh = 0.f;
    // self loop
    {
        float alS = (l < 8) ? g_alS1[w * 8 + l] : 0.f;
        float e = alS + alD;
        e = e > 0.f ? e : NEG * e;
        float pl = __expf(e);
        float p0 = __shfl_sync(0xFFFFFFFFu, pl, h0);
        float p1 = __shfl_sync(0xFFFFFFFFu, pl, h0 + 4);
        acc0 += p0 * g_h1[w * HID + l];
        acc1 += p1 * g_h1[w * HID + 32 + l];
        if (l < 8) sh += pl;
    }
    for (int j = 0; j < cnt; j++) {
        int src = g_eidx[beg + j];
        float alS = (l < 8) ? g_alS1[src * 8 + l] : 0.f;
        float e = alS + alD;
        e = e > 0.f ? e : NEG * e;
        float pl = __expf(e);
        float p0 = __shfl_sync(0xFFFFFFFFu, pl, h0);
        float p1 = __shfl_sync(0xFFFFFFFFu, pl, h0 + 4);
        acc0 += p0 * g_h1[src * HID + l];
        acc1 += p1 * g_h1[src * HID + 32 + l];
        if (l < 8) sh += pl;
    }
    float s0 = __shfl_sync(0xFFFFFFFFu, sh, h0);
    float s1 = __shfl_sync(0xFFFFFFFFu, sh, h0 + 4);
    float v0 = acc0 / s0 + b1[l];
    float v1 = acc1 / s1 + b1[32 + l];
    g_hact[w * HID + l]      = v0 > 0.f ? v0 : expm1f(v0);
    g_hact[w * HID + 32 + l] = v1 > 0.f ? v1 : expm1f(v1);
}

// ---------------- layer 2 GEMM: [N,64]@[64,40] + scalar logits ----------------
// 160 threads, 64 rows/block, thread = 4 rows x 4 cols
__global__ __launch_bounds__(160) void gemm2_k(
        const float* __restrict__ W2,
        const float* __restrict__ a_src2, const float* __restrict__ a_dst2, int n) {
    __shared__ float sW[HID * C2];   // 10KB
    __shared__ float sX[64 * HID];   // 16KB
    __shared__ float sLS[64];
    __shared__ float sLD[64];
    int t = threadIdx.x;
    int row0 = blockIdx.x * 64;
    for (int i = t; i < HID * C2; i += 160) sW[i] = W2[i];
    for (int i = t; i < 64 * HID; i += 160) {
        int r = i >> 6, c = i & 63;
        int gr = row0 + r;
        sX[i] = (gr < n) ? g_hact[gr * HID + c] : 0.f;
    }
    if (t < 64) { sLS[t] = 0.f; sLD[t] = 0.f; }
    __syncthreads();

    int cg = t % 10;   // cols cg*4..+3
    int rg = t / 10;   // rows rg*4..+3
    float acc[4][4];
#pragma unroll
    for (int r = 0; r < 4; r++)
#pragma unroll
        for (int c = 0; c < 4; c++) acc[r][c] = 0.f;

    const float4* sW4 = reinterpret_cast<const float4*>(sW);
#pragma unroll 4
    for (int k = 0; k < HID; k++) {
        float4 wv = sW4[k * 10 + cg];
        float xv0 = sX[(rg * 4 + 0) * HID + k];
        float xv1 = sX[(rg * 4 + 1) * HID + k];
        float xv2 = sX[(rg * 4 + 2) * HID + k];
        float xv3 = sX[(rg * 4 + 3) * HID + k];
#define STEP(r, xv) \
        acc[r][0] += xv * wv.x; acc[r][1] += xv * wv.y; \
        acc[r][2] += xv * wv.z; acc[r][3] += xv * wv.w;
        STEP(0, xv0) STEP(1, xv1) STEP(2, xv2) STEP(3, xv3)
#undef STEP
    }

#pragma unroll
    for (int r = 0; r < 4; r++) {
        int lr = rg * 4 + r;
        int gr = row0 + lr;
        float ps = 0.f, pd = 0.f;
#pragma unroll
        for (int j = 0; j < 4; j++) {
            int c = cg * 4 + j;
            if (gr < n) g_h2[gr * C2 + c] = acc[r][j];
            ps += acc[r][j] * a_src2[c];
            pd += acc[r][j] * a_dst2[c];
        }
        atomicAdd(&sLS[lr], ps);
        atomicAdd(&sLD[lr], pd);
    }
    __syncthreads();
    if (t < 64) {
        int gr = row0 + t;
        if (gr < n) { g_alS2[gr] = sLS[t]; g_alD2[gr] = sLD[t]; }
    }
}

// ---------------- layer 2 aggregation + log_softmax (warp per node) ----------------
__global__ __launch_bounds__(256) void agg2_k(const float* __restrict__ b2,
                                              float* __restrict__ out, int n) {
    int w = (blockIdx.x * blockDim.x + threadIdx.x) >> 5;
    if (w >= n) return;
    int l = threadIdx.x & 31;
    float alDv = g_alD2[w];
    int beg = g_rowstart[w], cnt = g_cnt[w];
    float acc0 = 0.f, acc1 = 0.f, s = 0.f;
    // self loop
    {
        float e = g_alS2[w] + alDv;
        e = e > 0.f ? e : NEG * e;
        float p = __expf(e);
        acc0 += p * g_h2[w * C2 + l];
        if (l < 8) acc1 += p * g_h2[w * C2 + 32 + l];
        s += p;
    }
    for (int j = 0; j < cnt; j++) {
        int src = g_eidx[beg + j];
        float e = g_alS2[src] + alDv;
        e = e > 0.f ? e : NEG * e;
        float p = __expf(e);
        acc0 += p * g_h2[src * C2 + l];
        if (l < 8) acc1 += p * g_h2[src * C2 + 32 + l];
        s += p;
    }
    float inv = 1.f / s;
    float v0 = acc0 * inv + b2[l];
    float v1 = (l < 8) ? (acc1 * inv + b2[32 + l]) : -3.0e38f;
    float m = fmaxf(v0, v1);
#pragma unroll
    for (int o = 16; o; o >>= 1) m = fmaxf(m, __shfl_xor_sync(0xFFFFFFFFu, m, o));
    float se = __expf(v0 - m) + ((l < 8) ? __expf(v1 - m) : 0.f);
#pragma unroll
    for (int o = 16; o; o >>= 1) se += __shfl_xor_sync(0xFFFFFFFFu, se, o);
    float lse = logf(se) + m;
    out[w * C2 + l] = v0 - lse;
    if (l < 8) out[w * C2 + 32 + l] = v1 - lse;
}

// ---------------- launcher ----------------
extern "C" void kernel_launch(void* const* d_in, const int* in_sizes, int n_in,
                              void* d_out, int out_size) {
    const float* x    = (const float*)d_in[0];
    const float* topo = (const float*)d_in[1];
    const int*   ei   = (const int*)d_in[2];
    const float* W1   = (const float*)d_in[3];
    const float* a_s1 = (const float*)d_in[4];
    const float* a_d1 = (const float*)d_in[5];
    const float* b1   = (const float*)d_in[6];
    const float* W2   = (const float*)d_in[7];
    const float* a_s2 = (const float*)d_in[8];
    const float* a_d2 = (const float*)d_in[9];
    const float* b2   = (const float*)d_in[10];
    float* out = (float*)d_out;

    int n = in_sizes[0] / 120;
    int E = in_sizes[2] / 2;
    int nb = (n + 1023) >> 10;

    cudaFuncSetAttribute(gemm1_k, cudaFuncAttributeMaxDynamicSharedMemorySize, 70656);

    // CSR build
    zero_cnt_k<<<(n + 255) / 256, 256>>>(n);
    count_k<<<(E + 255) / 256, 256>>>(ei, E);
    scanA_k<<<nb, 1024>>>(n);
    scanB_k<<<1, 32>>>(nb);
    scanC_k<<<(n + 255) / 256, 256>>>(n);
    scatter_k<<<(E + 255) / 256, 256>>>(ei, E);

    // layer 1
    gemm1_k<<<(n + 63) / 64, 256, 69632>>>(x, topo, W1, a_s1, a_d1, n);
    agg1_k<<<(n * 32 + 255) / 256, 256>>>(b1, n);

    // layer 2
    gemm2_k<<<(n + 63) / 64, 160>>>(W2, a_s2, a_d2, n);
    agg2_k<<<(n * 32 + 255) / 256, 256>>>(b2, out, n);
}